// round 3
// baseline (speedup 1.0000x reference)
#include <cuda_runtime.h>
#include <cuda_fp16.h>
#include <cstdint>
#include <cstddef>

// ---------------------------------------------------------------------------
// Model_6863357739715: LSTM(B=2048,S=512,F=64,H=32) -> MLP(32->32->16->3)
//
// K1: xg[s][b][unit*4+gate] = b[g] + sum_f x[b][s][f]*Wx[f][g]  (tf32 mma, fp16 out)
// K2: 1 batch-row per warp; Wh in 128 regs/lane; 512-step recurrence + MLP head.
// ---------------------------------------------------------------------------

#define B_SZ   2048
#define S_SZ   512
#define F_SZ   64
#define H_SZ   32
#define G4     128                 // 4*H
#define M_TOT  (B_SZ * S_SZ)       // 1048576
#define MTILES (M_TOT / 64)        // 16384

// 256 MB scratch: gate-packed input projections (+bias), fp16, layout [s][b][128].
__device__ __half g_xg_6863357739715[(size_t)S_SZ * B_SZ * G4];

// ---------------- helpers ----------------
__device__ __forceinline__ uint32_t f2tf32(float f) {
    uint32_t r;
    asm("cvt.rna.tf32.f32 %0, %1;" : "=r"(r) : "f"(f));
    return r;
}

__device__ __forceinline__ void mma_tf32(float d[4], const uint32_t a[4], const uint32_t b[2]) {
    asm volatile(
        "mma.sync.aligned.m16n8k8.row.col.f32.tf32.tf32.f32 "
        "{%0,%1,%2,%3}, {%4,%5,%6,%7}, {%8,%9}, {%0,%1,%2,%3};\n"
        : "+f"(d[0]), "+f"(d[1]), "+f"(d[2]), "+f"(d[3])
        : "r"(a[0]), "r"(a[1]), "r"(a[2]), "r"(a[3]), "r"(b[0]), "r"(b[1]));
}

__device__ __forceinline__ float sigm(float x) {
    return __fdividef(1.f, 1.f + __expf(-x));
}
__device__ __forceinline__ float tanh_(float x) {
    float ax = fabsf(x);
    float e  = __expf(-2.f * ax);
    float r  = __fdividef(1.f - e, 1.f + e);
    return copysignf(r, x);
}
__device__ __forceinline__ float lrelu(float x) {
    return x > 0.f ? x : 0.01f * x;
}

// ---------------------------------------------------------------------------
// K1: tall-skinny GEMM, M=1M, N=128, K=64, tf32 mma.sync m16n8k8.
// Block = 128 threads (4 warps); each warp computes an m16 x n128 tile.
// ---------------------------------------------------------------------------
__global__ void __launch_bounds__(128) k1_proj(const float* __restrict__ x,
                                               const float* __restrict__ Wx,
                                               const float* __restrict__ bvec) {
    __shared__ float2 sBf[8][16][32];   // [ktile][ntile][lane] = {b0,b1}, 32KB
    __shared__ float  sBias[128];       // bias in packed-n order

    const int t = threadIdx.x;

    if (t < 128) sBias[t] = bvec[(t & 3) * 32 + (t >> 2)];

    // Build B fragments once per block.
    for (int e = t; e < 8 * 16 * 32; e += 128) {
        int kt   = e >> 9;
        int nt   = (e >> 5) & 15;
        int lane = e & 31;
        int tg   = lane & 3;
        int gid  = lane >> 2;
        int k0   = kt * 8 + tg;              // b0 row (k), b1 at k0+4
        int n    = nt * 8 + gid;             // packed col: n = unit*4 + gate
        int g    = (n & 3) * 32 + (n >> 2);  // original column gate*32+unit
        float2 v;
        v.x = __uint_as_float(f2tf32(Wx[k0 * G4 + g]));
        v.y = __uint_as_float(f2tf32(Wx[(k0 + 4) * G4 + g]));
        sBf[kt][nt][lane] = v;
    }
    __syncthreads();

    const int warp = t >> 5;
    const int lane = t & 31;
    const int tg   = lane & 3;
    const int gid  = lane >> 2;

    // per-lane bias pair for each ntile (packed cols nt*8+2tg, +1)
    float2 bp[16];
#pragma unroll
    for (int nt = 0; nt < 16; ++nt) {
        bp[nt].x = sBias[nt * 8 + 2 * tg];
        bp[nt].y = sBias[nt * 8 + 2 * tg + 1];
    }

    for (int tile = blockIdx.x; tile < MTILES; tile += gridDim.x) {
        const int m0 = tile * 64 + warp * 16;

        uint32_t a[8][4];
        const float* xr0 = x + (size_t)(m0 + gid) * F_SZ;
        const float* xr8 = x + (size_t)(m0 + gid + 8) * F_SZ;
#pragma unroll
        for (int kt = 0; kt < 8; ++kt) {
            a[kt][0] = f2tf32(__ldg(xr0 + kt * 8 + tg));
            a[kt][1] = f2tf32(__ldg(xr8 + kt * 8 + tg));
            a[kt][2] = f2tf32(__ldg(xr0 + kt * 8 + tg + 4));
            a[kt][3] = f2tf32(__ldg(xr8 + kt * 8 + tg + 4));
        }

        float c[16][4];
#pragma unroll
        for (int nt = 0; nt < 16; ++nt) {
            c[nt][0] = 0.f; c[nt][1] = 0.f; c[nt][2] = 0.f; c[nt][3] = 0.f;
        }

#pragma unroll
        for (int kt = 0; kt < 8; ++kt) {
#pragma unroll
            for (int nt = 0; nt < 16; ++nt) {
                float2 bf = sBf[kt][nt][lane];
                uint32_t bb[2];
                bb[0] = __float_as_uint(bf.x);
                bb[1] = __float_as_uint(bf.y);
                mma_tf32(c[nt], a[kt], bb);
            }
        }

        // Store fp16: row m -> (b = m/512, s = m%512); out layout [s][b][128].
        const int r0 = m0 + gid, r1 = r0 + 8;
        __half* o0 = g_xg_6863357739715 +
                     ((size_t)(r0 & 511) * B_SZ + (r0 >> 9)) * G4 + 2 * tg;
        __half* o1 = g_xg_6863357739715 +
                     ((size_t)(r1 & 511) * B_SZ + (r1 >> 9)) * G4 + 2 * tg;
#pragma unroll
        for (int nt = 0; nt < 16; ++nt) {
            *(__half2*)(o0 + nt * 8) =
                __floats2half2_rn(c[nt][0] + bp[nt].x, c[nt][1] + bp[nt].y);
            *(__half2*)(o1 + nt * 8) =
                __floats2half2_rn(c[nt][2] + bp[nt].x, c[nt][3] + bp[nt].y);
        }
    }
}

// ---------------------------------------------------------------------------
// K2: recurrence. Block = 64 threads (2 warps). Warp w handles batch row
// blockIdx.x*2 + w; lane k owns hidden unit k. Wh lives in 128 regs per lane.
// h broadcast via double-buffered smem + one __syncwarp per step.
// Grid = 1024 blocks; 7 blocks/SM -> 14 warps/SM, one wave.
// ---------------------------------------------------------------------------
__global__ void __launch_bounds__(64, 7) k2_recur(
    const float* __restrict__ Wh,
    const float* __restrict__ W1, const float* __restrict__ b1v,
    const float* __restrict__ W2, const float* __restrict__ b2v,
    const float* __restrict__ Wo, const float* __restrict__ bov,
    float* __restrict__ out) {

    __shared__ float hs[2][2][32];   // [warp][buf][unit]
    __shared__ float a2s[2][16];     // MLP stage-2 activations

    const int lane = threadIdx.x & 31;
    const int wl   = threadIdx.x >> 5;
    const int row  = blockIdx.x * 2 + wl;

    // Wh packed per-lane: wh[j][g] = Wh[j][g*32 + lane]
    float wh[H_SZ][4];
#pragma unroll
    for (int j = 0; j < H_SZ; ++j) {
#pragma unroll
        for (int g = 0; g < 4; ++g)
            wh[j][g] = __ldg(Wh + j * G4 + g * 32 + lane);
    }

    hs[wl][0][lane] = 0.f;
    __syncwarp();

    // xg as uint2 = 4 halves (gates i,f,g,o of unit `lane`)
    const uint2* xp = (const uint2*)g_xg_6863357739715 + (size_t)row * 32 + lane;
    const size_t sstep = (size_t)B_SZ * 32;    // uint2 per timestep

    float cc = 0.f, hh = 0.f;
    uint2 xc = __ldg(xp);
    int p = 0;

#pragma unroll 1
    for (int s = 0; s < S_SZ; ++s) {
        uint2 xn = make_uint2(0u, 0u);
        if (s + 1 < S_SZ) xn = __ldg(xp + sstep);

        const __half2 xlo = *(const __half2*)&xc.x;
        const __half2 xhi = *(const __half2*)&xc.y;
        const float2 f01 = __half22float2(xlo);
        const float2 f23 = __half22float2(xhi);
        float zi = f01.x, zf = f01.y, zg = f23.x, zo = f23.y;

        const float4* hp = (const float4*)hs[wl][p];
#pragma unroll
        for (int j4 = 0; j4 < 8; ++j4) {
            const float4 hv = hp[j4];
            const int j = j4 * 4;
            zi += hv.x * wh[j][0];     zf += hv.x * wh[j][1];
            zg += hv.x * wh[j][2];     zo += hv.x * wh[j][3];
            zi += hv.y * wh[j + 1][0]; zf += hv.y * wh[j + 1][1];
            zg += hv.y * wh[j + 1][2]; zo += hv.y * wh[j + 1][3];
            zi += hv.z * wh[j + 2][0]; zf += hv.z * wh[j + 2][1];
            zg += hv.z * wh[j + 2][2]; zo += hv.z * wh[j + 2][3];
            zi += hv.w * wh[j + 3][0]; zf += hv.w * wh[j + 3][1];
            zg += hv.w * wh[j + 3][2]; zo += hv.w * wh[j + 3][3];
        }

        const float ig = sigm(zi), fg = sigm(zf), gg = tanh_(zg), og = sigm(zo);
        cc = fg * cc + ig * gg;
        hh = og * tanh_(cc);

        p ^= 1;
        hs[wl][p][lane] = hh;
        __syncwarp();

        xc = xn;
        xp += sstep;
    }

    // ------------- MLP head -------------
    const float* hf = hs[wl][p];
    float a1 = __ldg(b1v + lane);
#pragma unroll
    for (int j = 0; j < 32; ++j)
        a1 += hf[j] * __ldg(W1 + j * 32 + lane);
    a1 = lrelu(a1);

    hs[wl][p ^ 1][lane] = a1;
    __syncwarp();

    if (lane < 16) {
        const float* af = hs[wl][p ^ 1];
        float s2 = __ldg(b2v + lane);
#pragma unroll
        for (int j = 0; j < 32; ++j)
            s2 += af[j] * __ldg(W2 + j * 16 + lane);
        a2s[wl][lane] = lrelu(s2);
    }
    __syncwarp();

    if (lane < 3) {
        float ov = __ldg(bov + lane);
#pragma unroll
        for (int j = 0; j < 16; ++j)
            ov += a2s[wl][j] * __ldg(Wo + j * 3 + lane);
        out[row * 3 + lane] = ov;
    }
}

// ---------------------------------------------------------------------------
extern "C" void kernel_launch(void* const* d_in, const int* in_sizes, int n_in,
                              void* d_out, int out_size) {
    (void)in_sizes; (void)n_in; (void)out_size;
    const float* x    = (const float*)d_in[0];
    const float* Wx   = (const float*)d_in[1];
    const float* Wh   = (const float*)d_in[2];
    const float* bvec = (const float*)d_in[3];
    const float* W1   = (const float*)d_in[4];
    const float* b1v  = (const float*)d_in[5];
    const float* W2   = (const float*)d_in[6];
    const float* b2v  = (const float*)d_in[7];
    const float* Wo   = (const float*)d_in[8];
    const float* bov  = (const float*)d_in[9];

    k1_proj<<<2048, 128>>>(x, Wx, bvec);
    k2_recur<<<1024, 64>>>(Wh, W1, b1v, W2, b2v, Wo, bov, (float*)d_out);
}